// round 3
// baseline (speedup 1.0000x reference)
#include <cuda_runtime.h>

// Problem constants
#define BB 4
#define NN 4096
#define FF 15
#define AA 24
#define AFN 14
#define HID 10
#define KSEL 204
#define SCALE 0.31622776601683794f   // 1/sqrt(10)
#define RPB 8                        // rows per attn block
#define FULL 0xffffffffu

typedef unsigned long long ull;

// ---------------- scratch (device globals; no allocation allowed) ----------------
__device__ float g_q[BB * NN * HID];          // [b][n][d]
__device__ float g_kT[BB * HID * NN];         // [b][d][n]  (transposed, fp32)
__device__ float g_v[BB * NN * HID];          // [b][n][d]
__device__ float g_logits[BB * NN * 2];       // [b][n][c]

// ---------------- helpers ----------------
__device__ __forceinline__ unsigned orderf(float f) {
    unsigned u = __float_as_uint(f);
    return (u & 0x80000000u) ? ~u : (u | 0x80000000u);
}
__device__ __forceinline__ float unorderf(unsigned u) {
    return (u & 0x80000000u) ? __uint_as_float(u ^ 0x80000000u)
                             : __uint_as_float(~u);
}

// ---------------- Kernel 1: conv feature extraction + QKV projection ----------------
template <int H>
__device__ __forceinline__ float conv_one(const float* __restrict__ xp,
                                          const float* __restrict__ w, float bias) {
    constexpr int T = AA - H + 1;
    float y[T];
#pragma unroll
    for (int t = 0; t < T; t++) y[t] = 0.f;
#pragma unroll
    for (int i = 0; i < FF; i++) {
        float xr[AA];
#pragma unroll
        for (int t = 0; t < AA; t++) xr[t] = xp[i * AA + t];
#pragma unroll
        for (int dt = 0; dt < H; dt++) {
            float wv = w[i * H + dt];
#pragma unroll
            for (int t = 0; t < T; t++) y[t] += xr[t + dt] * wv;
        }
    }
    float m = y[0];
#pragma unroll
    for (int t = 1; t < T; t++) m = fmaxf(m, y[t]);
    return fmaxf(m + bias, 0.f);
}

#define XS 361  // padded seq stride in floats

__global__ __launch_bounds__(256) void conv_qkv_kernel(
    const float* __restrict__ x,
    const float* __restrict__ cw2, const float* __restrict__ cb2,
    const float* __restrict__ cw3, const float* __restrict__ cb3,
    const float* __restrict__ cw4, const float* __restrict__ cb4,
    const float* __restrict__ cw5, const float* __restrict__ cb5,
    const float* __restrict__ cw6, const float* __restrict__ cb6,
    const float* __restrict__ cw7, const float* __restrict__ cb7,
    const float* __restrict__ wq, const float* __restrict__ bq,
    const float* __restrict__ wk, const float* __restrict__ bk,
    const float* __restrict__ wv, const float* __restrict__ bv) {
    __shared__ float xs[16 * XS];
    __shared__ float fs[16][AFN];
    const int tid = threadIdx.x;
    const int sbase = blockIdx.x * 16;

    // cooperative vectorized load of 16 sequences of x (360 floats each)
    const float4* xg = (const float4*)(x + (size_t)sbase * (FF * AA));
    for (int i4 = tid; i4 < 16 * 90; i4 += 256) {
        float4 v = xg[i4];
        int s = i4 / 90, e4 = (i4 % 90) * 4;
        float* p = &xs[s * XS + e4];
        p[0] = v.x; p[1] = v.y; p[2] = v.z; p[3] = v.w;
    }
    __syncthreads();

    const int f = tid >> 4;
    const int s = tid & 15;
    if (f < AFN) {
        const float* xp = &xs[s * XS];
        float val;
        if (f < 3)       val = conv_one<2>(xp, cw2 + f * FF * 2, cb2[f]);
        else if (f < 6)  val = conv_one<3>(xp, cw3 + (f - 3) * FF * 3, cb3[f - 3]);
        else if (f < 9)  val = conv_one<4>(xp, cw4 + (f - 6) * FF * 4, cb4[f - 6]);
        else if (f < 11) val = conv_one<5>(xp, cw5 + (f - 9) * FF * 5, cb5[f - 9]);
        else if (f < 13) val = conv_one<6>(xp, cw6 + (f - 11) * FF * 6, cb6[f - 11]);
        else             val = conv_one<7>(xp, cw7, cb7[0]);
        fs[s][f] = val;
    }
    __syncthreads();

    // 480 work items (16 seqs x 3 proj x 10 outs) over 256 threads -> loop (was the R2 bug)
    for (int t = tid; t < 480; t += 256) {
        int s2 = t / 30, j = t % 30;
        int which = j / 10, o = j % 10;
        const float* W; const float* Bv;
        if (which == 0)      { W = wq; Bv = bq; }
        else if (which == 1) { W = wk; Bv = bk; }
        else                 { W = wv; Bv = bv; }
        float acc = Bv[o];
#pragma unroll
        for (int i = 0; i < AFN; i++) acc += fs[s2][i] * W[o * AFN + i];
        int seq = sbase + s2;
        int b = seq >> 12, n = seq & 4095;
        if (which == 0)      g_q[(b * NN + n) * HID + o] = acc;
        else if (which == 1) g_kT[(b * HID + o) * NN + n] = acc;
        else                 g_v[(b * NN + n) * HID + o] = acc;
    }
}

// ---------------- Kernel 2: scores (block-wide) + per-warp row pipeline ----------------
// dynamic smem layout (bytes):
#define KEYS_OFF 0                         // RPB * NN * 4   = 131072
#define CAND_OFF (RPB * NN * 4)            // RPB * 256 * 8  = 16384
#define HIST_OFF (CAND_OFF + RPB * 2048)   // RPB * 256 * 4  = 8192
#define SHQ_OFF  (HIST_OFF + RPB * 1024)   // RPB * HID * 4  = 320
#define SMEM_TOTAL (SHQ_OFF + RPB * HID * 4)

__global__ __launch_bounds__(256, 1) void attn_kernel(
    const float* __restrict__ wattn, const float* __restrict__ battn,
    const float* __restrict__ wmil, const float* __restrict__ bmil,
    float* __restrict__ out) {
    extern __shared__ unsigned char smem_raw[];
    unsigned* keys = (unsigned*)(smem_raw + KEYS_OFF);
    ull*      cand = (ull*)(smem_raw + CAND_OFF);
    unsigned* hist = (unsigned*)(smem_raw + HIST_OFF);
    float*    shq  = (float*)(smem_raw + SHQ_OFF);

    const int b = blockIdx.y;
    const int r0 = blockIdx.x * RPB;
    const int tid = threadIdx.x;
    const int lane = tid & 31;
    const int wid = tid >> 5;

    if (tid < RPB * HID) shq[tid] = g_q[((size_t)b * NN + r0) * HID + tid];
    __syncthreads();

    // ---- Phase A: scores for 8 rows, ordered keys -> smem ----
    const float* kt = g_kT + (size_t)b * HID * NN;
#pragma unroll
    for (int g = 0; g < 2; g++) {
        const int jb = g * 2048 + tid * 8;
        float acc[RPB][8];
#pragma unroll
        for (int r = 0; r < RPB; r++)
#pragma unroll
            for (int i = 0; i < 8; i++) acc[r][i] = 0.f;
#pragma unroll
        for (int d = 0; d < HID; d++) {
            float4 k0 = *(const float4*)(kt + d * NN + jb);
            float4 k1 = *(const float4*)(kt + d * NN + jb + 4);
            float kk[8] = {k0.x, k0.y, k0.z, k0.w, k1.x, k1.y, k1.z, k1.w};
#pragma unroll
            for (int r = 0; r < RPB; r++) {
                float qv = shq[r * HID + d];
#pragma unroll
                for (int i = 0; i < 8; i++) acc[r][i] += qv * kk[i];
            }
        }
#pragma unroll
        for (int r = 0; r < RPB; r++) {
            uint4 o0, o1;
            o0.x = orderf(acc[r][0]); o0.y = orderf(acc[r][1]);
            o0.z = orderf(acc[r][2]); o0.w = orderf(acc[r][3]);
            o1.x = orderf(acc[r][4]); o1.y = orderf(acc[r][5]);
            o1.z = orderf(acc[r][6]); o1.w = orderf(acc[r][7]);
            *(uint4*)(keys + r * NN + jb)     = o0;
            *(uint4*)(keys + r * NN + jb + 4) = o1;
        }
    }
    __syncthreads();

    // ---- Phase B: warp `wid` owns row r0+wid, fully warp-local ----
    unsigned* krow = keys + wid * NN;
    unsigned* hrow = hist + wid * 256;
    ull*      crow = cand + wid * 256;

    // 4-pass radix select: exact key of the 204th-largest score
    unsigned pref = 0;
    int kneed = KSEL;
#pragma unroll
    for (int pass = 0; pass < 4; pass++) {
#pragma unroll
        for (int i = 0; i < 8; i++) hrow[lane * 8 + i] = 0u;
        __syncwarp();
        const int shift = 24 - 8 * pass;
        if (pass == 0) {
            for (int j = 0; j < 128; j++) {
                unsigned u = krow[j * 32 + lane];
                atomicAdd(&hrow[u >> 24], 1u);
            }
        } else {
            for (int j = 0; j < 128; j++) {
                unsigned u = krow[j * 32 + lane];
                if ((u >> (shift + 8)) == pref)
                    atomicAdd(&hrow[(u >> shift) & 255u], 1u);
            }
        }
        __syncwarp();
        unsigned h8[8];
        int part = 0;
#pragma unroll
        for (int i = 0; i < 8; i++) { h8[i] = hrow[lane * 8 + i]; part += (int)h8[i]; }
        int suff = part;
#pragma unroll
        for (int d2 = 1; d2 < 32; d2 <<= 1) {
            int v = __shfl_down_sync(FULL, suff, d2);
            if (lane + d2 < 32) suff += v;
        }
        int c = suff - part;            // count of keys in buckets > lane*8+7
        unsigned bsel = 0; int krem = 0; bool found = false;
#pragma unroll
        for (int i = 7; i >= 0; i--) {
            int Cn = c;
            c += (int)h8[i];
            if (!found && c >= kneed && Cn < kneed) {
                bsel = (unsigned)(lane * 8 + i);
                krem = kneed - Cn;
                found = true;
            }
        }
        unsigned fm = __ballot_sync(FULL, found);
        int src = __ffs(fm) - 1;
        pref = (pref << 8) | __shfl_sync(FULL, bsel, src);
        kneed = __shfl_sync(FULL, krem, src);
        __syncwarp();
    }
    const unsigned T = pref;

    // collect candidates u >= T (>= 204 of them), compacted by ballot
#pragma unroll
    for (int i = 0; i < 8; i++) crow[lane * 8 + i] = 0ull;
    __syncwarp();
    unsigned base = 0;
    for (int j = 0; j < 128; j++) {
        unsigned u = krow[j * 32 + lane];
        bool p = (u >= T);
        unsigned mm = __ballot_sync(FULL, p);
        if (p) {
            unsigned pos = base + __popc(mm & ((1u << lane) - 1u));
            if (pos < 256u)
                crow[pos] = ((ull)u << 32) | (ull)(~(unsigned)(j * 32 + lane));
        }
        base += __popc(mm);
    }
    __syncwarp();

    // in-register bitonic sort of 256 elems, 8 per thread; element index i = e*32+lane
    // composite key desc == (value desc, index asc) -> exact lax.top_k order
    ull v8[8];
#pragma unroll
    for (int e = 0; e < 8; e++) v8[e] = crow[e * 32 + lane];

#pragma unroll
    for (int k2 = 2; k2 <= 256; k2 <<= 1) {
#pragma unroll
        for (int j = 128; j > 0; j >>= 1) {
            if (j >= k2) continue;
            if (j >= 32) {
                const int jj = j >> 5;
#pragma unroll
                for (int e = 0; e < 8; e++) {
                    if (e & jj) continue;
                    int ilo = e * 32 + lane;
                    bool up = ((ilo & k2) == 0);
                    ull a = v8[e], bb = v8[e | jj];
                    bool sw = up ? (a < bb) : (a > bb);
                    if (sw) { v8[e] = bb; v8[e | jj] = a; }
                }
            } else {
#pragma unroll
                for (int e = 0; e < 8; e++) {
                    int i = e * 32 + lane;
                    bool up = ((i & k2) == 0);
                    ull other = __shfl_xor_sync(FULL, v8[e], j);
                    bool lower = ((lane & j) == 0);
                    bool takemax = (up == lower);
                    ull mx = (v8[e] > other) ? v8[e] : other;
                    ull mn = (v8[e] > other) ? other : v8[e];
                    v8[e] = takemax ? mx : mn;
                }
            }
        }
    }

    // ---- softmax over top-204 (scaled), exact ref ordering ----
    unsigned topu = __shfl_sync(FULL, (unsigned)(v8[0] >> 32), 0);
    const float smax = unorderf(topu) * SCALE;
    float ex[7];
    float sum = 0.f;
#pragma unroll
    for (int e = 0; e < 7; e++) {
        int rank = e * 32 + lane;
        float sv = unorderf((unsigned)(v8[e] >> 32)) * SCALE;
        float ee = (rank < KSEL) ? __expf(sv - smax) : 0.f;
        ex[e] = ee;
        sum += ee;
    }
#pragma unroll
    for (int off = 16; off > 0; off >>= 1) sum += __shfl_xor_sync(FULL, sum, off);
    const float inv = 1.f / sum;

    // ---- probs out + V gather + context ----
    const float* vbase = g_v + (size_t)b * NN * HID;
    float* orow = out + 8 + ((size_t)(b * NN + r0 + wid)) * KSEL;
    float cd[HID];
#pragma unroll
    for (int d = 0; d < HID; d++) cd[d] = 0.f;
#pragma unroll
    for (int e = 0; e < 7; e++) {
        int rank = e * 32 + lane;
        if (rank < KSEL) {
            float p = ex[e] * inv;
            orow[rank] = p;
            unsigned gidx = ~(unsigned)(v8[e] & 0xffffffffull);
            const float2* vp = (const float2*)(vbase + (size_t)gidx * HID);
            float2 a0 = vp[0], a1 = vp[1], a2 = vp[2], a3 = vp[3], a4 = vp[4];
            cd[0] += p * a0.x; cd[1] += p * a0.y;
            cd[2] += p * a1.x; cd[3] += p * a1.y;
            cd[4] += p * a2.x; cd[5] += p * a2.y;
            cd[6] += p * a3.x; cd[7] += p * a3.y;
            cd[8] += p * a4.x; cd[9] += p * a4.y;
        }
    }
#pragma unroll
    for (int d = 0; d < HID; d++)
#pragma unroll
        for (int off = 16; off > 0; off >>= 1)
            cd[d] += __shfl_xor_sync(FULL, cd[d], off);
    // all lanes now hold the full context vector cd[0..9]

    // attn proj (lane < 14 computes one output), then mil proj via reductions
    float sa = 0.f;
    if (lane < AFN) {
        sa = battn[lane];
#pragma unroll
        for (int d = 0; d < HID; d++) sa += cd[d] * wattn[lane * HID + d];
    }
    float t0 = (lane < AFN) ? sa * wmil[lane] : 0.f;
    float t1 = (lane < AFN) ? sa * wmil[AFN + lane] : 0.f;
#pragma unroll
    for (int off = 16; off > 0; off >>= 1) {
        t0 += __shfl_xor_sync(FULL, t0, off);
        t1 += __shfl_xor_sync(FULL, t1, off);
    }
    if (lane == 0) {
        int row = b * NN + r0 + wid;
        g_logits[row * 2 + 0] = t0 + bmil[0];
        g_logits[row * 2 + 1] = t1 + bmil[1];
    }
}

// ---------------- Kernel 3: deterministic pooled reduction ----------------
__global__ __launch_bounds__(256) void pool_kernel(float* __restrict__ out) {
    int w = threadIdx.x >> 5, l = threadIdx.x & 31;
    if (w < 8) {
        int b = w >> 1, c = w & 1;
        float acc = 0.f;
        for (int n = l; n < NN; n += 32) acc += g_logits[(b * NN + n) * 2 + c];
#pragma unroll
        for (int off = 16; off > 0; off >>= 1) acc += __shfl_down_sync(FULL, acc, off);
        if (l == 0) out[b * 2 + c] = acc * (1.0f / (float)NN);
    }
}

// ---------------- launcher ----------------
extern "C" void kernel_launch(void* const* d_in, const int* in_sizes, int n_in,
                              void* d_out, int out_size) {
    const float* x   = (const float*)d_in[0];
    const float* cw2 = (const float*)d_in[1];  const float* cb2 = (const float*)d_in[2];
    const float* cw3 = (const float*)d_in[3];  const float* cb3 = (const float*)d_in[4];
    const float* cw4 = (const float*)d_in[5];  const float* cb4 = (const float*)d_in[6];
    const float* cw5 = (const float*)d_in[7];  const float* cb5 = (const float*)d_in[8];
    const float* cw6 = (const float*)d_in[9];  const float* cb6 = (const float*)d_in[10];
    const float* cw7 = (const float*)d_in[11]; const float* cb7 = (const float*)d_in[12];
    const float* wq  = (const float*)d_in[13]; const float* bq  = (const float*)d_in[14];
    const float* wk  = (const float*)d_in[15]; const float* bk  = (const float*)d_in[16];
    const float* wv  = (const float*)d_in[17]; const float* bv  = (const float*)d_in[18];
    const float* wat = (const float*)d_in[19]; const float* bat = (const float*)d_in[20];
    const float* wm  = (const float*)d_in[21]; const float* bm  = (const float*)d_in[22];
    float* out = (float*)d_out;

    cudaFuncSetAttribute(attn_kernel, cudaFuncAttributeMaxDynamicSharedMemorySize, SMEM_TOTAL);

    conv_qkv_kernel<<<(BB * NN) / 16, 256>>>(x, cw2, cb2, cw3, cb3, cw4, cb4,
                                             cw5, cb5, cw6, cb6, cw7, cb7,
                                             wq, bq, wk, bk, wv, bv);
    attn_kernel<<<dim3(NN / RPB, BB), 256, SMEM_TOTAL>>>(wat, bat, wm, bm, out);
    pool_kernel<<<1, 256>>>(out);
}